// round 3
// baseline (speedup 1.0000x reference)
#include <cuda_runtime.h>
#include <math.h>

#define SQ 2048   // sequence length
#define BB 64     // batch
#define DI 512    // input dim
#define HD 512    // hidden dim
#define G4 2048   // 4*HD

#define NBLK 128          // persistent blocks (<=148 SMs, co-resident)
#define COLS_PER_BLK 16   // gate columns per block
#define HPAD 516          // padded h row (floats) -> conflict-free LDS.128

// ---- device scratch (allocation-free; __device__ globals per the rules) ----
__device__ float g_xproj[2048ULL * 64ULL * 2048ULL];  // 1 GiB: x @ W_ih^T
__device__ float g_gates[BB * G4];                    // activated gates [b][gc]
__device__ unsigned long long g_bar;                  // grid barrier ticket counter

__device__ __forceinline__ float sigf(float x) { return 1.0f / (1.0f + __expf(-x)); }

// Grid-wide barrier: monotonic ticket counter (u64: never overflows across replays;
// every launch adds a multiple of NBLK, so generation math stays consistent).
__device__ __forceinline__ void gridbar(unsigned nb) {
    __threadfence();
    __syncthreads();
    if (threadIdx.x == 0) {
        unsigned long long t = atomicAdd(&g_bar, 1ULL) + 1ULL;
        unsigned long long target = ((t + nb - 1ULL) / nb) * (unsigned long long)nb;
        while (*((volatile unsigned long long*)&g_bar) < target) { }
        __threadfence();
    }
    __syncthreads();
}

// ============================================================================
// Kernel 1: x_proj[m][n] = sum_k x[m][k] * W_ih[n][k]
// M = SQ*BB = 131072, N = G4 = 2048, K = DI = 512
// 128x128 block tile, BK=8, 256 threads, 8x8 microtile.
// ============================================================================
__global__ __launch_bounds__(256, 2)
void xproj_gemm(const float* __restrict__ A, const float* __restrict__ W)
{
    __shared__ float As[8][128];
    __shared__ float Bs[8][128];

    const int bn  = blockIdx.x;          // 0..15
    const int bm  = blockIdx.y;          // 0..1023
    const int tid = threadIdx.x;

    const int arow = tid >> 1;           // 0..127
    const int acol = (tid & 1) << 2;     // 0 or 4
    const float* Ag = A + (size_t)(bm * 128 + arow) * DI + acol;
    const float* Wg = W + (size_t)(bn * 128 + arow) * DI + acol;

    const int tx = tid & 15;             // col group (8 cols each)
    const int ty = tid >> 4;             // row group (8 rows each)

    float acc[8][8];
#pragma unroll
    for (int i = 0; i < 8; i++)
#pragma unroll
        for (int j = 0; j < 8; j++) acc[i][j] = 0.0f;

    for (int kt = 0; kt < DI; kt += 8) {
        float4 av = *(const float4*)(Ag + kt);
        float4 wv = *(const float4*)(Wg + kt);
        __syncthreads();
        As[acol + 0][arow] = av.x; As[acol + 1][arow] = av.y;
        As[acol + 2][arow] = av.z; As[acol + 3][arow] = av.w;
        Bs[acol + 0][arow] = wv.x; Bs[acol + 1][arow] = wv.y;
        Bs[acol + 2][arow] = wv.z; Bs[acol + 3][arow] = wv.w;
        __syncthreads();
#pragma unroll
        for (int k = 0; k < 8; k++) {
            float ar[8], br[8];
            *(float4*)(ar)     = *(const float4*)&As[k][ty * 8];
            *(float4*)(ar + 4) = *(const float4*)&As[k][ty * 8 + 4];
            *(float4*)(br)     = *(const float4*)&Bs[k][tx * 8];
            *(float4*)(br + 4) = *(const float4*)&Bs[k][tx * 8 + 4];
#pragma unroll
            for (int i = 0; i < 8; i++)
#pragma unroll
                for (int j = 0; j < 8; j++)
                    acc[i][j] += ar[i] * br[j];
        }
    }

    float* Cp = g_xproj + (size_t)(bm * 128 + ty * 8) * G4 + (size_t)(bn * 128 + tx * 8);
#pragma unroll
    for (int i = 0; i < 8; i++) {
        *(float4*)(Cp + (size_t)i * G4)     = make_float4(acc[i][0], acc[i][1], acc[i][2], acc[i][3]);
        *(float4*)(Cp + (size_t)i * G4 + 4) = make_float4(acc[i][4], acc[i][5], acc[i][6], acc[i][7]);
    }
}

// ============================================================================
// Kernel 2: persistent LSTM recurrence.
// 128 blocks x 256 threads. Block owns 16 gate columns (all within one gate
// type). W_hh slice resident in SMEM for all 2048 steps; h staged per step.
// Phase A: gates = act(xproj + h @ W^T + bias)  -> g_gates   [barrier]
// Phase B: c = f*c + i*g; h = o*tanh(c) -> d_out (doubles as state) [barrier]
// ============================================================================
__global__ __launch_bounds__(256, 1)
void lstm_persist(const float* __restrict__ Whh,
                  const float* __restrict__ bih,
                  const float* __restrict__ bhh,
                  float* __restrict__ out)
{
    extern __shared__ float smem[];
    float* h_s    = smem;                       // BB * HPAD floats
    float* w_s    = smem + BB * HPAD;           // 16 * 512 floats
    float* bias_s = w_s + COLS_PER_BLK * HD;    // 16 floats

    const int tid = threadIdx.x;
    const int bid = blockIdx.x;
    const int c0  = bid * COLS_PER_BLK;

    float* out_h = out;
    float* out_c = out + (size_t)SQ * BB * HD;

    // One-time: load W_hh slice (rows c0..c0+15) and combined bias.
    {
        const float4* wg  = (const float4*)(Whh + (size_t)c0 * HD);
        float4*       ws4 = (float4*)w_s;
        for (int i = tid; i < COLS_PER_BLK * (HD / 4); i += 256) ws4[i] = wg[i];
        if (tid < COLS_PER_BLK) bias_s[tid] = bih[c0 + tid] + bhh[c0 + tid];
    }
    const bool use_tanh = ((c0 >> 9) == 2);     // gate g -> tanh; i,f,o -> sigmoid

    const int warp  = tid >> 5;
    const int lane  = tid & 31;
    const int bb    = ((warp & 1) << 5) + lane; // batch index 0..63
    const int cbase = (warp >> 1) << 2;         // local col base 0,4,8,12

    for (int t = 0; t < SQ; ++t) {
        // ---- stage h_{t-1} into padded SMEM ----
        if (t == 0) {
            for (int i = tid; i < BB * HPAD; i += 256) h_s[i] = 0.0f;
        } else {
            const float4* hp = (const float4*)(out_h + (size_t)(t - 1) * BB * HD);
            for (int i = tid; i < BB * (HD / 4); i += 256) {
                int b = i >> 7, u = i & 127;
                *(float4*)(h_s + b * HPAD + (u << 2)) = hp[i];
            }
        }
        __syncthreads();

        // ---- Phase A: recurrent GEMM for (batch bb) x 4 columns ----
        float4 a0 = make_float4(0.f, 0.f, 0.f, 0.f);
        float4 a1 = a0, a2 = a0, a3 = a0;
        const float4* hrow = (const float4*)(h_s + bb * HPAD);
        const float4* w0 = (const float4*)(w_s + (cbase + 0) * HD);
        const float4* w1 = (const float4*)(w_s + (cbase + 1) * HD);
        const float4* w2 = (const float4*)(w_s + (cbase + 2) * HD);
        const float4* w3 = (const float4*)(w_s + (cbase + 3) * HD);
#pragma unroll 8
        for (int k = 0; k < HD / 4; ++k) {
            float4 hv = hrow[k];
            float4 v;
            v = w0[k]; a0.x += hv.x * v.x; a0.y += hv.y * v.y; a0.z += hv.z * v.z; a0.w += hv.w * v.w;
            v = w1[k]; a1.x += hv.x * v.x; a1.y += hv.y * v.y; a1.z += hv.z * v.z; a1.w += hv.w * v.w;
            v = w2[k]; a2.x += hv.x * v.x; a2.y += hv.y * v.y; a2.z += hv.z * v.z; a2.w += hv.w * v.w;
            v = w3[k]; a3.x += hv.x * v.x; a3.y += hv.y * v.y; a3.z += hv.z * v.z; a3.w += hv.w * v.w;
        }
        float s0 = (a0.x + a0.y) + (a0.z + a0.w);
        float s1 = (a1.x + a1.y) + (a1.z + a1.w);
        float s2 = (a2.x + a2.y) + (a2.z + a2.w);
        float s3 = (a3.x + a3.y) + (a3.z + a3.w);

        {
            size_t xi = (size_t)t * (BB * G4) + (size_t)bb * G4 + (size_t)(c0 + cbase);
            float4 xp = *(const float4*)(g_xproj + xi);
            float v0 = s0 + xp.x + bias_s[cbase + 0];
            float v1 = s1 + xp.y + bias_s[cbase + 1];
            float v2 = s2 + xp.z + bias_s[cbase + 2];
            float v3 = s3 + xp.w + bias_s[cbase + 3];
            float4 r;
            if (use_tanh) {
                r.x = tanhf(v0); r.y = tanhf(v1); r.z = tanhf(v2); r.w = tanhf(v3);
            } else {
                r.x = sigf(v0);  r.y = sigf(v1);  r.z = sigf(v2);  r.w = sigf(v3);
            }
            *(float4*)(g_gates + (size_t)bb * G4 + (size_t)(c0 + cbase)) = r;
        }
        gridbar(NBLK);

        // ---- Phase B: elementwise state update (fully coalesced) ----
        {
            int idx = bid * 256 + tid;          // 0..32767 == BB*HD
            int b = idx >> 9, j = idx & 511;
            const float* gb = g_gates + (size_t)b * G4;
            float iv = gb[j];
            float fv = gb[512 + j];
            float gv = gb[1024 + j];
            float ov = gb[1536 + j];
            float cprev = (t == 0) ? 0.0f : out_c[(size_t)(t - 1) * BB * HD + (b << 9) + j];
            float cc = fv * cprev + iv * gv;
            float hh = ov * tanhf(cc);
            size_t o = (size_t)t * BB * HD + (size_t)(b << 9) + j;
            out_c[o] = cc;
            out_h[o] = hh;
        }
        gridbar(NBLK);
    }
}

// ============================================================================
// Launch: inputs per metadata order: x, W_ih, W_hh, b_ih, b_hh.
// Output: [h_out (S,B,H) | c_out (S,B,H)] float32.
// ============================================================================
extern "C" void kernel_launch(void* const* d_in, const int* in_sizes, int n_in,
                              void* d_out, int out_size)
{
    (void)in_sizes; (void)n_in; (void)out_size;
    const float* x   = (const float*)d_in[0];
    const float* Wih = (const float*)d_in[1];
    const float* Whh = (const float*)d_in[2];
    const float* bih = (const float*)d_in[3];
    const float* bhh = (const float*)d_in[4];
    float* out = (float*)d_out;

    const int smem_bytes = (BB * HPAD + COLS_PER_BLK * HD + COLS_PER_BLK) * (int)sizeof(float);
    cudaFuncSetAttribute(lstm_persist, cudaFuncAttributeMaxDynamicSharedMemorySize, smem_bytes);

    dim3 g1(G4 / 128, (SQ * BB) / 128);   // (16, 1024)
    xproj_gemm<<<g1, 256>>>(x, Wih);
    lstm_persist<<<NBLK, 256, smem_bytes>>>(Whh, bih, bhh, out);
}